// round 1
// baseline (speedup 1.0000x reference)
#include <cuda_runtime.h>
#include <cuda_bf16.h>

#define NN 8192
#define T  64
#define NT (NN / T)   // 128 tiles per dim

// Scratch (no device-side allocation allowed): deterministic partial row sums
// g_part[k][i] = contribution to degree d[i] from tile-column k. 4 MB.
__device__ float g_part[NT * NN];
__device__ float g_dis[NN];

// ---------------------------------------------------------------------------
// Pass 1: for each tile pair (bi <= bj), load A = adj[I,J] and B = adj[J,I],
// form M = max(A, B^T) (diag forced to 1 on diagonal tiles), and emit:
//   rowsum_c M[r][c] -> g_part[bj][I0+r]
//   rowsum_r M[r][c] -> g_part[bi][J0+c]   (off-diagonal pairs only)
// Every slot g_part[k][i] is written exactly once -> fully deterministic.
// ---------------------------------------------------------------------------
__global__ __launch_bounds__(256) void pass1_degrees(const float* __restrict__ adj) {
    const int bi = blockIdx.y, bj = blockIdx.x;
    if (bj < bi) return;

    __shared__ float As[T][T + 1];
    __shared__ float Bs[T][T + 1];

    const int t  = threadIdx.x;
    const int I0 = bi * T, J0 = bj * T;

    // Coalesced float4 loads: 16 threads x float4 per 64-float row, 16 rows/wave
    const int c4 = (t & 15) * 4;
    const int rw = t >> 4;
    #pragma unroll
    for (int rr = rw; rr < T; rr += 16) {
        float4 a = *reinterpret_cast<const float4*>(&adj[(size_t)(I0 + rr) * NN + J0 + c4]);
        As[rr][c4 + 0] = a.x; As[rr][c4 + 1] = a.y;
        As[rr][c4 + 2] = a.z; As[rr][c4 + 3] = a.w;
        float4 b = *reinterpret_cast<const float4*>(&adj[(size_t)(J0 + rr) * NN + I0 + c4]);
        Bs[rr][c4 + 0] = b.x; Bs[rr][c4 + 1] = b.y;
        Bs[rr][c4 + 2] = b.z; Bs[rr][c4 + 3] = b.w;
    }
    __syncthreads();

    // Row sums: 4 threads per row, 16 columns each, shfl-combine
    {
        const int r  = t >> 2;
        const int cb = (t & 3) * 16;
        float s = 0.0f;
        #pragma unroll
        for (int c = cb; c < cb + 16; ++c) {
            float v = fmaxf(As[r][c], Bs[c][r]);
            if (bi == bj && r == c) v = 1.0f;
            s += v;
        }
        s += __shfl_xor_sync(0xffffffffu, s, 1);
        s += __shfl_xor_sync(0xffffffffu, s, 2);
        if ((t & 3) == 0) g_part[bj * NN + I0 + r] = s;
    }

    // Column sums (contribution to rows J0+c) for off-diagonal pairs
    if (bi != bj) {
        const int c  = t >> 2;
        const int rb = (t & 3) * 16;
        float s = 0.0f;
        #pragma unroll
        for (int r = rb; r < rb + 16; ++r)
            s += fmaxf(As[r][c], Bs[c][r]);
        s += __shfl_xor_sync(0xffffffffu, s, 1);
        s += __shfl_xor_sync(0xffffffffu, s, 2);
        if ((t & 3) == 0) g_part[bi * NN + J0 + c] = s;
    }
}

// ---------------------------------------------------------------------------
// Reduce the 128 partials per row and take rsqrt. Coalesced: thread i reads
// g_part[k*NN + i] for k = 0..127.
// ---------------------------------------------------------------------------
__global__ __launch_bounds__(256) void reduce_rsqrt_kernel() {
    const int i = blockIdx.x * blockDim.x + threadIdx.x;
    if (i >= NN) return;
    float s = 0.0f;
    #pragma unroll 8
    for (int k = 0; k < NT; ++k)
        s += g_part[k * NN + i];
    g_dis[i] = rsqrtf(s);
}

// ---------------------------------------------------------------------------
// Pass 2: re-load the tile pair, recompute M = max(A, B^T), scale by
// dis[row]*dis[col], write out[I,J] and (off-diagonal) out[J,I]. All smem
// reads are conflict-free via the +1 padding; all global stores coalesced.
// ---------------------------------------------------------------------------
__global__ __launch_bounds__(256) void pass2_write(const float* __restrict__ adj,
                                                   float* __restrict__ out) {
    const int bi = blockIdx.y, bj = blockIdx.x;
    if (bj < bi) return;

    __shared__ float As[T][T + 1];
    __shared__ float Bs[T][T + 1];
    __shared__ float dI[T], dJ[T];

    const int t  = threadIdx.x;
    const int I0 = bi * T, J0 = bj * T;

    const int c4 = (t & 15) * 4;
    const int rw = t >> 4;
    #pragma unroll
    for (int rr = rw; rr < T; rr += 16) {
        float4 a = *reinterpret_cast<const float4*>(&adj[(size_t)(I0 + rr) * NN + J0 + c4]);
        As[rr][c4 + 0] = a.x; As[rr][c4 + 1] = a.y;
        As[rr][c4 + 2] = a.z; As[rr][c4 + 3] = a.w;
        float4 b = *reinterpret_cast<const float4*>(&adj[(size_t)(J0 + rr) * NN + I0 + c4]);
        Bs[rr][c4 + 0] = b.x; Bs[rr][c4 + 1] = b.y;
        Bs[rr][c4 + 2] = b.z; Bs[rr][c4 + 3] = b.w;
    }
    if (t < T)            dI[t]     = g_dis[I0 + t];
    else if (t < 2 * T)   dJ[t - T] = g_dis[J0 + (t - T)];
    __syncthreads();

    const int c  = t & 63;
    const int r0 = t >> 6;   // 4 row-groups

    // out[I,J]: thread lanes span c -> coalesced stores; Bs[c][r] conflict-free
    #pragma unroll
    for (int r = r0; r < T; r += 4) {
        float v = fmaxf(As[r][c], Bs[c][r]);
        if (bi == bj && r == c) v = 1.0f;
        out[(size_t)(I0 + r) * NN + J0 + c] = v * dI[r] * dJ[c];
    }

    // out[J,I] (transpose block), skip for diagonal tiles (already complete)
    if (bi != bj) {
        #pragma unroll
        for (int r = r0; r < T; r += 4) {  // r = row within the (J,I) block
            float v = fmaxf(Bs[r][c], As[c][r]);
            out[(size_t)(J0 + r) * NN + I0 + c] = v * dJ[r] * dI[c];
        }
    }
}

extern "C" void kernel_launch(void* const* d_in, const int* in_sizes, int n_in,
                              void* d_out, int out_size) {
    const float* adj = (const float*)d_in[0];
    float*       out = (float*)d_out;

    dim3 grid(NT, NT);
    pass1_degrees<<<grid, 256>>>(adj);
    reduce_rsqrt_kernel<<<NN / 256, 256>>>();
    pass2_write<<<grid, 256>>>(adj, out);
}

// round 3
// speedup vs baseline: 1.1410x; 1.1410x over previous
#include <cuda_runtime.h>
#include <cuda_bf16.h>

#define NN 8192
#define T  64
#define NT (NN / T)   // 128

// Deterministic partial row sums: g_part[k][i] = degree contribution to row i
// from tile-column k. Written exactly once per slot. 4 MB scratch.
__device__ float g_part[NT * NN];
__device__ float g_dis[NN];

// ---------------------------------------------------------------------------
// Pass 1 (degrees): tile pair (bi <= bj). Only B = adj[J,I] staged in smem;
// A = adj[I,J] read straight from global in compute layout. Each smem element
// read exactly once; m accumulated into BOTH row partials (shfl-reduce) and
// column partials (per-thread register, since each thread owns one column).
// Thread map: c = t & 63 (column), rg = t >> 6 (16-row group).
// ---------------------------------------------------------------------------
__global__ __launch_bounds__(256) void pass1_degrees(const float* __restrict__ adj) {
    const int bi = blockIdx.y, bj = blockIdx.x;
    if (bj < bi) return;

    __shared__ float Bs[T][T + 1];
    __shared__ float rpart[T][2];
    __shared__ float cpart[4][T];

    const int t    = threadIdx.x;
    const int c    = t & 63;
    const int rg   = t >> 6;
    const int half = (t >> 5) & 1;        // which 32-column half this warp covers
    const size_t I0 = (size_t)bi * T, J0 = (size_t)bj * T;

    // Load B tile (coalesced; STS bank = (rr + c) % 32 via lane-c spread -> conflict-free)
    #pragma unroll
    for (int k = 0; k < 16; ++k) {
        int rr = rg * 16 + k;
        Bs[rr][c] = adj[(J0 + rr) * NN + I0 + c];
    }
    __syncthreads();

    const bool diag = (bi == bj);
    float colAcc = 0.0f;

    #pragma unroll
    for (int k = 0; k < 16; ++k) {
        int r = rg * 16 + k;
        float a = adj[(I0 + r) * NN + J0 + c];          // coalesced
        float m = fmaxf(a, Bs[c][r]);                    // bank (c+r)%32 -> conflict-free
        if (diag && r == c) m = 1.0f;
        colAcc += m;
        float s = m;                                     // row-sum reduce across the 32 lanes (c-half)
        s += __shfl_xor_sync(0xffffffffu, s, 1);
        s += __shfl_xor_sync(0xffffffffu, s, 2);
        s += __shfl_xor_sync(0xffffffffu, s, 4);
        s += __shfl_xor_sync(0xffffffffu, s, 8);
        s += __shfl_xor_sync(0xffffffffu, s, 16);
        if ((t & 31) == 0) rpart[r][half] = s;
    }
    cpart[rg][c] = colAcc;
    __syncthreads();

    if (t < T) {
        g_part[bj * NN + I0 + t] = rpart[t][0] + rpart[t][1];
        if (!diag)
            g_part[bi * NN + J0 + t] = cpart[0][t] + cpart[1][t] + cpart[2][t] + cpart[3][t];
    }
}

// ---------------------------------------------------------------------------
// Reduce the 128 partials per row, rsqrt. Coalesced.
// ---------------------------------------------------------------------------
__global__ __launch_bounds__(256) void reduce_rsqrt_kernel() {
    const int i = blockIdx.x * blockDim.x + threadIdx.x;
    if (i >= NN) return;
    float s = 0.0f;
    #pragma unroll 8
    for (int k = 0; k < NT; ++k)
        s += g_part[k * NN + i];
    g_dis[i] = rsqrtf(s);
}

// ---------------------------------------------------------------------------
// Pass 2 (write): out is SYMMETRIC, so the (J,I) block is the transpose of
// the (I,J) block. Compute scaled value s once, write out[I,J] coalesced,
// stage s in place over the Bs slot just read (bijective per-thread read ->
// no hazard), then one transposed conflict-free re-read writes out[J,I].
// Blocks walk tile pairs in REVERSE of pass1 order for L2 reuse.
// ---------------------------------------------------------------------------
__global__ __launch_bounds__(256) void pass2_write(const float* __restrict__ adj,
                                                   float* __restrict__ out) {
    const int bx = blockIdx.x, by = blockIdx.y;
    if (bx > by) return;                  // reversed triangle
    const int bi = NT - 1 - by, bj = NT - 1 - bx;   // bj >= bi

    __shared__ float Bs[T][T + 1];
    __shared__ float dI[T], dJ[T];

    const int t  = threadIdx.x;
    const int c  = t & 63;
    const int rg = t >> 6;
    const size_t I0 = (size_t)bi * T, J0 = (size_t)bj * T;

    #pragma unroll
    for (int k = 0; k < 16; ++k) {
        int rr = rg * 16 + k;
        Bs[rr][c] = adj[(J0 + rr) * NN + I0 + c];
    }
    if (t < T)          dI[t]     = g_dis[I0 + t];
    else if (t < 2 * T) dJ[t - T] = g_dis[J0 + (t - T)];
    __syncthreads();

    const bool diag = (bi == bj);
    const float djc = dJ[c];

    #pragma unroll
    for (int k = 0; k < 16; ++k) {
        int r = rg * 16 + k;
        float a = adj[(I0 + r) * NN + J0 + c];
        float m = fmaxf(a, Bs[c][r]);
        if (diag && r == c) m = 1.0f;
        float s = m * dI[r] * djc;
        out[(I0 + r) * NN + J0 + c] = s;  // coalesced
        Bs[c][r] = s;                     // stage transposed (same slot just read)
    }

    if (!diag) {
        __syncthreads();
        #pragma unroll
        for (int k = 0; k < 16; ++k) {
            int rr = rg * 16 + k;         // row within the (J,I) block
            out[(J0 + rr) * NN + I0 + c] = Bs[rr][c];   // conflict-free, coalesced
        }
    }
}

extern "C" void kernel_launch(void* const* d_in, const int* in_sizes, int n_in,
                              void* d_out, int out_size) {
    const float* adj = (const float*)d_in[0];
    float*       out = (float*)d_out;

    dim3 grid(NT, NT);
    pass1_degrees<<<grid, 256>>>(adj);
    reduce_rsqrt_kernel<<<NN / 256, 256>>>();
    pass2_write<<<grid, 256>>>(adj, out);
}